// round 14
// baseline (speedup 1.0000x reference)
#include <cuda_runtime.h>
#include <cuda_bf16.h>
#include <cstdint>

// ===========================================================================
// Compile-time CG machinery (all constexpr, double precision)
// ===========================================================================
__host__ __device__ constexpr double cfct(int k) {
    double r = 1.0;
    for (int i = 2; i <= k; ++i) r *= (double)i;
    return r;
}
__host__ __device__ constexpr double csqrt(double x) {
    if (x <= 0.0) return 0.0;
    double g = x < 1.0 ? 1.0 : x;
    for (int i = 0; i < 40; ++i) g = 0.5 * (g + x / g);
    return g;
}
__host__ __device__ constexpr double csu2(int j1,int m1,int j2,int m2,int j3,int m3) {
    if (m1 + m2 != m3) return 0.0;
    if (m3 > j3 || m3 < -j3) return 0.0;
    int vmin = -j1 + j2 + m3; if (-j1 + m1 > vmin) vmin = -j1 + m1; if (vmin < 0) vmin = 0;
    int vmax = j2 + j3 + m1; if (j3 - j1 + j2 < vmax) vmax = j3 - j1 + j2; if (j3 + m3 < vmax) vmax = j3 + m3;
    if (vmax < vmin) return 0.0;
    double C = (2.0*j3 + 1.0)
             * (cfct(j3+j1-j2)*cfct(j3-j1+j2)*cfct(j1+j2-j3)*cfct(j3+m3)*cfct(j3-m3))
             / (cfct(j1+j2+j3+1)*cfct(j1-m1)*cfct(j1+m1)*cfct(j2-m2)*cfct(j2+m2));
    double S = 0.0;
    for (int v = vmin; v <= vmax; ++v) {
        double t = (cfct(j2+j3+m1-v)*cfct(j1-m1+v))
                 / (cfct(v)*cfct(j3-j1+j2-v)*cfct(j3+m3-v)*cfct(v+j1-j2-m3));
        S += (((v + j2 + m2) & 1) ? -t : t);
    }
    return csqrt(C) * S;
}

struct cc { double r, i; };
__host__ __device__ constexpr cc cmulc(cc a, cc b) {
    return cc{a.r*b.r - a.i*b.i, a.r*b.i + a.i*b.r};
}
__host__ __device__ constexpr cc qent(int l, int mu, int m) {
    const double invs = 0.70710678118654752440;
    cc q{0.0, 0.0};
    if (mu == 0) {
        if (m != 0) return cc{0.0, 0.0};
        q = cc{1.0, 0.0};
    } else if (mu < 0) {
        if (m == -mu)      q = cc{invs, 0.0};
        else if (m == mu)  q = cc{0.0, -invs};
        else return cc{0.0, 0.0};
    } else {
        if (m == mu)       q = cc{(mu & 1) ? -invs : invs, 0.0};
        else if (m == -mu) q = cc{0.0, (mu & 1) ? -invs : invs};
        else return cc{0.0, 0.0};
    }
    cc o{0.0, 0.0};
    switch (l & 3) {
        case 0: o = q; break;
        case 1: o = cc{ q.i, -q.r}; break;
        case 2: o = cc{-q.r, -q.i}; break;
        default: o = cc{-q.i,  q.r}; break;
    }
    return o;
}
__host__ __device__ constexpr double ccgreal(int l1,int m1,int l2,int m2,int l3,int m3) {
    double acc = 0.0;
    int am1 = m1 < 0 ? -m1 : m1;
    int am2 = m2 < 0 ? -m2 : m2;
    for (int s1 = 0; s1 < 2; ++s1) {
        if (am1 == 0 && s1 == 1) continue;
        int mu1 = s1 ? -am1 : am1;
        cc q1 = qent(l1, mu1, m1);
        for (int s2 = 0; s2 < 2; ++s2) {
            if (am2 == 0 && s2 == 1) continue;
            int mu2 = s2 ? -am2 : am2;
            int mu3 = mu1 + mu2;
            if (mu3 > l3 || mu3 < -l3) continue;
            cc q3 = qent(l3, mu3, m3);
            if (q3.r == 0.0 && q3.i == 0.0) continue;
            q3.i = -q3.i;
            double cg = csu2(l1, mu1, l2, mu2, l3, mu3);
            if (cg == 0.0) continue;
            cc t = cmulc(cmulc(q1, qent(l2, mu2, m2)), q3);
            acc += t.r * cg;
        }
    }
    return acc;
}

__host__ __device__ constexpr int pathof(int lo, int l1, int l2) {
    const signed char L[64] = {
       0,-1,-1,-1, -1, 1,-1,-1, -1,-1, 2,-1, -1,-1,-1, 3,
      -1, 4,-1,-1,  5,-1, 6,-1, -1, 7,-1, 8, -1,-1, 9,-1,
      -1,-1,10,-1, -1,11,-1,12, 13,-1,14,-1, -1,15,-1,16,
      -1,-1,-1,17, -1,-1,18,-1, -1,19,-1,20, 21,-1,22,-1
    };
    return L[lo*16 + l1*4 + l2];
}

__host__ __device__ constexpr bool term_ok(int l1,int m1,int l2,int m2,int lo,int m3) {
    if ((l1 + l2 + lo) & 1) return false;
    int dl = l1 - l2; if (dl < 0) dl = -dl;
    if (lo < dl || lo > l1 + l2) return false;
    int am1 = m1 < 0 ? -m1 : m1;
    int am2 = m2 < 0 ? -m2 : m2;
    int am3 = m3 < 0 ? -m3 : m3;
    int s = am1 + am2;
    int d = am1 - am2; if (d < 0) d = -d;
    if (am3 != s && am3 != d) return false;
    if ((((m1 < 0) ? 1 : 0) + ((m2 < 0) ? 1 : 0) + ((m3 < 0) ? 1 : 0)) & 1) return false;
    return true;
}

struct CGT { float v[4096]; };
__host__ __device__ constexpr CGT make_cgt() {
    CGT t{};
    for (int a = 0; a < 16; ++a)
    for (int b = 0; b < 16; ++b)
    for (int c = 0; c < 16; ++c) {
        int l1 = (a >= 9) ? 3 : (a >= 4) ? 2 : (a >= 1) ? 1 : 0;
        int l2 = (b >= 9) ? 3 : (b >= 4) ? 2 : (b >= 1) ? 1 : 0;
        int lo = (c >= 9) ? 3 : (c >= 4) ? 2 : (c >= 1) ? 1 : 0;
        int m1 = a - l1*l1 - l1;
        int m2 = b - l2*l2 - l2;
        int m3 = c - lo*lo - lo;
        double val = 0.0;
        if (pathof(lo, l1, l2) >= 0 && term_ok(l1, m1, l2, m2, lo, m3))
            val = csqrt(2.0*lo + 1.0) * ccgreal(l1, m1, l2, m2, lo, m3);
        t.v[(a*16 + b)*16 + c] = (float)val;
    }
    return t;
}

// ===========================================================================
// Scalar compute core (FFMA-imm CG constants) — identical to R9/R10.
// ===========================================================================
__device__ __forceinline__ void compute_row(const float X1[16], const float X2[16],
                                            const float* __restrict__ weights,
                                            float AC[16]) {
    static constexpr CGT CG = make_cgt();
    #pragma unroll
    for (int i = 0; i < 16; ++i) AC[i] = 0.f;

    #pragma unroll
    for (int l1 = 0; l1 <= 3; ++l1)
    #pragma unroll
    for (int l2 = 0; l2 <= 3; ++l2)
    #pragma unroll
    for (int lo = 0; lo <= 3; ++lo) {
        if ((l1 + l2 + lo) & 1) continue;
        {
            const int dl = l1 > l2 ? l1 - l2 : l2 - l1;
            if (lo < dl || lo > l1 + l2) continue;
        }
        const int p = pathof(lo, l1, l2);
        if (p < 0) continue;

        float t[7];
        #pragma unroll
        for (int i = 0; i < 7; ++i) t[i] = 0.f;

        #pragma unroll
        for (int m1 = -3; m1 <= 3; ++m1) {
            if (m1 < -l1 || m1 > l1) continue;
            #pragma unroll
            for (int m2 = -3; m2 <= 3; ++m2) {
                if (m2 < -l2 || m2 > l2) continue;
                const int a = l1*l1 + l1 + m1;
                const int b = l2*l2 + l2 + m2;
                const float pa = X1[a] * X2[b];
                #pragma unroll
                for (int m3 = -3; m3 <= 3; ++m3) {
                    if (m3 < -lo || m3 > lo) continue;
                    if (!term_ok(l1, m1, l2, m2, lo, m3)) continue;
                    const int c = lo*lo + lo + m3;
                    const float cg = CG.v[(a*16 + b)*16 + c];
                    if (cg == 0.f) continue;
                    t[lo + m3] = fmaf(cg, pa, t[lo + m3]);
                }
            }
        }
        const float wp = __ldg(weights + p);
        #pragma unroll
        for (int m3 = -lo; m3 <= lo; ++m3) {
            const int c = lo*lo + lo + m3;
            AC[c] = fmaf(wp, t[lo + m3], AC[c]);
        }
    }
}

// XOR swizzle in float4 units (involution): conflict-free for both the
// coalesced pattern (v = k*32+lane) and the row pattern (v = 4*lane+i).
__device__ __forceinline__ int sw4(int v) { return v ^ ((v >> 3) & 3); }

// ===========================================================================
// Persistent kernel, R10 latency-hiding shape with coalesced global access:
// per-warp private smem staging (sync LDG->STS->LDS), no block barriers.
// Wavefronts/warp-trip: 192 (R10) -> 144.
// ===========================================================================
__global__ void __launch_bounds__(256)
tp_main(const float* __restrict__ x1, const float* __restrict__ x2,
        const float* __restrict__ weights, float* __restrict__ out, int n) {
    __shared__ __align__(16) float4 smem[8 * 256];   // 8 warps x (128 f4 x1 + 128 f4 x2)
    const int lane = threadIdx.x & 31;
    const int w    = threadIdx.x >> 5;
    float4* d1 = smem + w * 256;        // x1 slice (reused for output staging)
    float4* d2 = d1 + 128;              // x2 slice

    const int nwt = (n + 31) >> 5;      // warp-tiles of 32 rows
    const int wstride = gridDim.x * 8;

    for (int wt = blockIdx.x * 8 + w; wt < nwt; wt += wstride) {
        const int rowbase = wt << 5;
        const bool full = (rowbase + 32 <= n);

        // ---- coalesced front-batched loads (8 independent LDG.128) ----
        float4 A1[4], A2[4];
        {
            const float4* g1 = (const float4*)x1 + (size_t)rowbase * 4;
            const float4* g2 = (const float4*)x2 + (size_t)rowbase * 4;
            #pragma unroll
            for (int k = 0; k < 4; ++k) {
                const int v = k * 32 + lane;
                if (full || rowbase + (v >> 2) < n) { A1[k] = g1[v]; A2[k] = g2[v]; }
            }
        }

        // ---- stage to smem (swizzled, conflict-free) ----
        #pragma unroll
        for (int k = 0; k < 4; ++k) {
            const int sv = sw4(k * 32 + lane);
            d1[sv] = A1[k];
            d2[sv] = A2[k];
        }
        __syncwarp();

        // ---- row-ordered reads (conflict-free) ----
        float X1[16], X2[16], AC[16];
        #pragma unroll
        for (int i = 0; i < 4; ++i) {
            const int sv = sw4(4 * lane + i);
            float4 a = d1[sv];
            X1[4*i] = a.x; X1[4*i+1] = a.y; X1[4*i+2] = a.z; X1[4*i+3] = a.w;
            float4 b = d2[sv];
            X2[4*i] = b.x; X2[4*i+1] = b.y; X2[4*i+2] = b.z; X2[4*i+3] = b.w;
        }

        compute_row(X1, X2, weights, AC);

        // ---- stage output into d1 (x1 data fully consumed), then
        //      coalesced STG.128 ----
        __syncwarp();
        #pragma unroll
        for (int i = 0; i < 4; ++i) {
            const int sv = sw4(4 * lane + i);
            d1[sv] = make_float4(AC[4*i], AC[4*i+1], AC[4*i+2], AC[4*i+3]);
        }
        __syncwarp();
        {
            float4* g = (float4*)out + (size_t)rowbase * 4;
            #pragma unroll
            for (int k = 0; k < 4; ++k) {
                const int v = k * 32 + lane;
                if (full || rowbase + (v >> 2) < n) g[v] = d1[sw4(v)];
            }
        }
        __syncwarp();   // stage reusable next trip
    }
}

extern "C" void kernel_launch(void* const* d_in, const int* in_sizes, int n_in,
                              void* d_out, int out_size) {
    const float* x1 = (const float*)d_in[0];
    const float* x2 = (const float*)d_in[1];
    const float* weights = (const float*)d_in[2];
    float* out = (float*)d_out;
    const int n = in_sizes[0] / 16;

    int dev = 0, nsm = 148, perSm = 0;
    cudaGetDevice(&dev);
    cudaDeviceGetAttribute(&nsm, cudaDevAttrMultiProcessorCount, dev);
    cudaOccupancyMaxActiveBlocksPerMultiprocessor(&perSm, tp_main, 256, 0);
    if (perSm < 1) perSm = 1;

    int blocks = nsm * perSm;
    const int work_blocks = (n + 255) / 256;
    if (blocks > work_blocks) blocks = work_blocks;

    tp_main<<<blocks, 256>>>(x1, x2, weights, out, n);
}

// round 15
// speedup vs baseline: 1.6080x; 1.6080x over previous
#include <cuda_runtime.h>
#include <cuda_bf16.h>

// ===========================================================================
// Compile-time CG machinery (all constexpr, double precision)
// ===========================================================================
__host__ __device__ constexpr double cfct(int k) {
    double r = 1.0;
    for (int i = 2; i <= k; ++i) r *= (double)i;
    return r;
}
__host__ __device__ constexpr double csqrt(double x) {
    if (x <= 0.0) return 0.0;
    double g = x < 1.0 ? 1.0 : x;
    for (int i = 0; i < 40; ++i) g = 0.5 * (g + x / g);
    return g;
}
__host__ __device__ constexpr double csu2(int j1,int m1,int j2,int m2,int j3,int m3) {
    if (m1 + m2 != m3) return 0.0;
    if (m3 > j3 || m3 < -j3) return 0.0;
    int vmin = -j1 + j2 + m3; if (-j1 + m1 > vmin) vmin = -j1 + m1; if (vmin < 0) vmin = 0;
    int vmax = j2 + j3 + m1; if (j3 - j1 + j2 < vmax) vmax = j3 - j1 + j2; if (j3 + m3 < vmax) vmax = j3 + m3;
    if (vmax < vmin) return 0.0;
    double C = (2.0*j3 + 1.0)
             * (cfct(j3+j1-j2)*cfct(j3-j1+j2)*cfct(j1+j2-j3)*cfct(j3+m3)*cfct(j3-m3))
             / (cfct(j1+j2+j3+1)*cfct(j1-m1)*cfct(j1+m1)*cfct(j2-m2)*cfct(j2+m2));
    double S = 0.0;
    for (int v = vmin; v <= vmax; ++v) {
        double t = (cfct(j2+j3+m1-v)*cfct(j1-m1+v))
                 / (cfct(v)*cfct(j3-j1+j2-v)*cfct(j3+m3-v)*cfct(v+j1-j2-m3));
        S += (((v + j2 + m2) & 1) ? -t : t);
    }
    return csqrt(C) * S;
}

struct cc { double r, i; };
__host__ __device__ constexpr cc cmulc(cc a, cc b) {
    return cc{a.r*b.r - a.i*b.i, a.r*b.i + a.i*b.r};
}
__host__ __device__ constexpr cc qent(int l, int mu, int m) {
    const double invs = 0.70710678118654752440;
    cc q{0.0, 0.0};
    if (mu == 0) {
        if (m != 0) return cc{0.0, 0.0};
        q = cc{1.0, 0.0};
    } else if (mu < 0) {
        if (m == -mu)      q = cc{invs, 0.0};
        else if (m == mu)  q = cc{0.0, -invs};
        else return cc{0.0, 0.0};
    } else {
        if (m == mu)       q = cc{(mu & 1) ? -invs : invs, 0.0};
        else if (m == -mu) q = cc{0.0, (mu & 1) ? -invs : invs};
        else return cc{0.0, 0.0};
    }
    cc o{0.0, 0.0};
    switch (l & 3) {
        case 0: o = q; break;
        case 1: o = cc{ q.i, -q.r}; break;
        case 2: o = cc{-q.r, -q.i}; break;
        default: o = cc{-q.i,  q.r}; break;
    }
    return o;
}
__host__ __device__ constexpr double ccgreal(int l1,int m1,int l2,int m2,int l3,int m3) {
    double acc = 0.0;
    int am1 = m1 < 0 ? -m1 : m1;
    int am2 = m2 < 0 ? -m2 : m2;
    for (int s1 = 0; s1 < 2; ++s1) {
        if (am1 == 0 && s1 == 1) continue;
        int mu1 = s1 ? -am1 : am1;
        cc q1 = qent(l1, mu1, m1);
        for (int s2 = 0; s2 < 2; ++s2) {
            if (am2 == 0 && s2 == 1) continue;
            int mu2 = s2 ? -am2 : am2;
            int mu3 = mu1 + mu2;
            if (mu3 > l3 || mu3 < -l3) continue;
            cc q3 = qent(l3, mu3, m3);
            if (q3.r == 0.0 && q3.i == 0.0) continue;
            q3.i = -q3.i;
            double cg = csu2(l1, mu1, l2, mu2, l3, mu3);
            if (cg == 0.0) continue;
            cc t = cmulc(cmulc(q1, qent(l2, mu2, m2)), q3);
            acc += t.r * cg;
        }
    }
    return acc;
}

__host__ __device__ constexpr int pathof(int lo, int l1, int l2) {
    const signed char L[64] = {
       0,-1,-1,-1, -1, 1,-1,-1, -1,-1, 2,-1, -1,-1,-1, 3,
      -1, 4,-1,-1,  5,-1, 6,-1, -1, 7,-1, 8, -1,-1, 9,-1,
      -1,-1,10,-1, -1,11,-1,12, 13,-1,14,-1, -1,15,-1,16,
      -1,-1,-1,17, -1,-1,18,-1, -1,19,-1,20, 21,-1,22,-1
    };
    return L[lo*16 + l1*4 + l2];
}

__host__ __device__ constexpr bool term_ok(int l1,int m1,int l2,int m2,int lo,int m3) {
    if ((l1 + l2 + lo) & 1) return false;
    int dl = l1 - l2; if (dl < 0) dl = -dl;
    if (lo < dl || lo > l1 + l2) return false;
    int am1 = m1 < 0 ? -m1 : m1;
    int am2 = m2 < 0 ? -m2 : m2;
    int am3 = m3 < 0 ? -m3 : m3;
    int s = am1 + am2;
    int d = am1 - am2; if (d < 0) d = -d;
    if (am3 != s && am3 != d) return false;
    if ((((m1 < 0) ? 1 : 0) + ((m2 < 0) ? 1 : 0) + ((m3 < 0) ? 1 : 0)) & 1) return false;
    return true;
}

struct CGT { float v[4096]; };
__host__ __device__ constexpr CGT make_cgt() {
    CGT t{};
    for (int a = 0; a < 16; ++a)
    for (int b = 0; b < 16; ++b)
    for (int c = 0; c < 16; ++c) {
        int l1 = (a >= 9) ? 3 : (a >= 4) ? 2 : (a >= 1) ? 1 : 0;
        int l2 = (b >= 9) ? 3 : (b >= 4) ? 2 : (b >= 1) ? 1 : 0;
        int lo = (c >= 9) ? 3 : (c >= 4) ? 2 : (c >= 1) ? 1 : 0;
        int m1 = a - l1*l1 - l1;
        int m2 = b - l2*l2 - l2;
        int m3 = c - lo*lo - lo;
        double val = 0.0;
        if (pathof(lo, l1, l2) >= 0 && term_ok(l1, m1, l2, m2, lo, m3))
            val = csqrt(2.0*lo + 1.0) * ccgreal(l1, m1, l2, m2, lo, m3);
        t.v[(a*16 + b)*16 + c] = (float)val;
    }
    return t;
}

// ===========================================================================
// Main kernel — byte-identical R10 structure (best measured: 64.0 us), with
// cache-streaming (evict-first) loads and stores: all traffic is touch-once,
// so keeping it out of L2 residency avoids read/write stream thrash.
// ===========================================================================
__global__ void __launch_bounds__(256)
tp_main(const float* __restrict__ x1, const float* __restrict__ x2,
        const float* __restrict__ weights, float* __restrict__ out, int n) {
    static constexpr CGT CG = make_cgt();

    const int stride = gridDim.x * 256;
    for (int r = blockIdx.x * 256 + threadIdx.x; r < n; r += stride) {

        float X1[16], X2[16], AC[16];
        {
            const float4* q1 = (const float4*)x1 + (size_t)r * 4;
            const float4* q2 = (const float4*)x2 + (size_t)r * 4;
            #pragma unroll
            for (int i = 0; i < 4; ++i) {
                float4 a = __ldcs(q1 + i);            // LDG.E.CS (evict-first)
                X1[4*i] = a.x; X1[4*i+1] = a.y; X1[4*i+2] = a.z; X1[4*i+3] = a.w;
                float4 b = __ldcs(q2 + i);
                X2[4*i] = b.x; X2[4*i+1] = b.y; X2[4*i+2] = b.z; X2[4*i+3] = b.w;
            }
        }
        #pragma unroll
        for (int i = 0; i < 16; ++i) AC[i] = 0.f;

        // Path-major: t[m3] += cg_imm * (x1[a]*x2[b]); AC += w_p * t.
        #pragma unroll
        for (int l1 = 0; l1 <= 3; ++l1)
        #pragma unroll
        for (int l2 = 0; l2 <= 3; ++l2)
        #pragma unroll
        for (int lo = 0; lo <= 3; ++lo) {
            if ((l1 + l2 + lo) & 1) continue;
            {
                const int dl = l1 > l2 ? l1 - l2 : l2 - l1;
                if (lo < dl || lo > l1 + l2) continue;
            }
            const int p = pathof(lo, l1, l2);
            if (p < 0) continue;

            float t[7];
            #pragma unroll
            for (int i = 0; i < 7; ++i) t[i] = 0.f;

            #pragma unroll
            for (int m1 = -3; m1 <= 3; ++m1) {
                if (m1 < -l1 || m1 > l1) continue;
                #pragma unroll
                for (int m2 = -3; m2 <= 3; ++m2) {
                    if (m2 < -l2 || m2 > l2) continue;
                    const int a = l1*l1 + l1 + m1;
                    const int b = l2*l2 + l2 + m2;
                    const float pa = X1[a] * X2[b];               // CSE'd across lo
                    #pragma unroll
                    for (int m3 = -3; m3 <= 3; ++m3) {
                        if (m3 < -lo || m3 > lo) continue;
                        if (!term_ok(l1, m1, l2, m2, lo, m3)) continue;
                        const int c = lo*lo + lo + m3;
                        const float cg = CG.v[(a*16 + b)*16 + c]; // folds to imm
                        if (cg == 0.f) continue;
                        t[lo + m3] = fmaf(cg, pa, t[lo + m3]);    // FFMA-imm
                    }
                }
            }
            const float wp = __ldg(weights + p);
            #pragma unroll
            for (int m3 = -lo; m3 <= lo; ++m3) {
                const int c = lo*lo + lo + m3;
                AC[c] = fmaf(wp, t[lo + m3], AC[c]);
            }
        }

        {
            float4* q = (float4*)out + (size_t)r * 4;
            #pragma unroll
            for (int i = 0; i < 4; ++i)
                __stcs(q + i, make_float4(AC[4*i], AC[4*i+1], AC[4*i+2], AC[4*i+3]));  // STG.CS
        }
    }
}

extern "C" void kernel_launch(void* const* d_in, const int* in_sizes, int n_in,
                              void* d_out, int out_size) {
    const float* x1 = (const float*)d_in[0];
    const float* x2 = (const float*)d_in[1];
    const float* weights = (const float*)d_in[2];
    float* out = (float*)d_out;
    const int n = in_sizes[0] / 16;

    // Persistent sizing: exactly fill the chip (host-side queries only;
    // graph-capture safe, no allocation).
    int dev = 0, nsm = 148, perSm = 0;
    cudaGetDevice(&dev);
    cudaDeviceGetAttribute(&nsm, cudaDevAttrMultiProcessorCount, dev);
    cudaOccupancyMaxActiveBlocksPerMultiprocessor(&perSm, tp_main, 256, 0);
    if (perSm < 1) perSm = 1;

    int blocks = nsm * perSm;
    const int work_blocks = (n + 255) / 256;
    if (blocks > work_blocks) blocks = work_blocks;

    tp_main<<<blocks, 256>>>(x1, x2, weights, out, n);
}